// round 5
// baseline (speedup 1.0000x reference)
#include <cuda_runtime.h>
#include <cstdint>
#include <cstddef>

#define NA 4096
#define TT 512
#define TS 384
#define AS 128
#define AZ 16
#define NFEAT 388

__device__ int   g_tok[NA];
__device__ float g_s2c[TT * AS];
__device__ float g_cq[NA * AZ];
__device__ float g_ck[NA * AZ];

// ---- kernel 1: token id per atom (argmax of one-hot row) ----
__global__ void tok_kernel(const float* __restrict__ a2t) {
    int row = blockIdx.x * 8 + (threadIdx.x >> 5);
    int lane = threadIdx.x & 31;
    if (row >= NA) return;
    const float* r = a2t + (size_t)row * TT;
    int found = -1;
    for (int j = lane; j < TT; j += 32)
        if (r[j] > 0.5f) found = j;
#pragma unroll
    for (int d = 16; d; d >>= 1) found = max(found, __shfl_xor_sync(~0u, found, d));
    if (lane == 0) g_tok[row] = found;
}

// ---- kernel 2: s2c = LN(s_trunk) @ W_s2c  (4 rows/block, 256 thr) ----
__global__ void s2c_kernel(const float* __restrict__ s_trunk,
                           const float* __restrict__ g, const float* __restrict__ b,
                           const float* __restrict__ W) {
    __shared__ float srow[4 * TS];
    __shared__ float mu[4], rsd[4];
    int r0 = blockIdx.x * 4, tid = threadIdx.x;
    for (int i = tid; i < 4 * TS; i += 256) srow[i] = s_trunk[(size_t)r0 * TS + i];
    __syncthreads();
    int wid = tid >> 5, lane = tid & 31;
    if (wid < 4) {
        float s = 0.f, q = 0.f;
        for (int f = lane; f < TS; f += 32) { float v = srow[wid * TS + f]; s += v; q += v * v; }
#pragma unroll
        for (int d = 16; d; d >>= 1) { s += __shfl_xor_sync(~0u, s, d); q += __shfl_xor_sync(~0u, q, d); }
        if (lane == 0) { float m = s / TS; mu[wid] = m; rsd[wid] = rsqrtf(q / TS - m * m + 1e-5f); }
    }
    __syncthreads();
    for (int i = tid; i < 4 * TS; i += 256) {
        int r = i / TS, f = i - r * TS;
        srow[i] = (srow[i] - mu[r]) * rsd[r] * g[f] + b[f];
    }
    __syncthreads();
    int o = tid & 127, hp = tid >> 7;
    const float* ra = &srow[(hp * 2) * TS];
    const float* rb = &srow[(hp * 2 + 1) * TS];
    float a0 = 0.f, a1 = 0.f;
    for (int f = 0; f < TS; f++) {
        float w = W[(size_t)f * AS + o];
        a0 += ra[f] * w; a1 += rb[f] * w;
    }
    g_s2c[(r0 + hp * 2) * AS + o] = a0;
    g_s2c[(r0 + hp * 2 + 1) * AS + o] = a1;
}

// ---- kernel 3: c0 = feats@W_feat+b ; q and c=q+s2c[tok] outputs ----
__global__ void __launch_bounds__(256) c0_kernel(
    const float* __restrict__ pos, const float* __restrict__ charge,
    const float* __restrict__ elem, const float* __restrict__ chars,
    const float* __restrict__ Wf, const float* __restrict__ bf,
    float* __restrict__ out_q, float* __restrict__ out_c) {
    __shared__ float As[16][40];
    __shared__ float Bs[16][128];
    int tid = threadIdx.x, ty = tid >> 5, tx = tid & 31;
    int m0 = blockIdx.x * 32;
    float acc[4][4] = {};
    for (int kt = 0; kt < 25; kt++) {
        int fbase = kt * 16;
#pragma unroll
        for (int j = 0; j < 2; j++) {
            int e = tid + j * 256;
            int kk = e & 15, m = e >> 4;
            int f = fbase + kk, n = m0 + m;
            float v = 0.f;
            if (f < NFEAT) {
                if (f < 3)        v = pos[n * 3 + f];
                else if (f == 3)  v = charge[n];
                else if (f < 132) v = elem[(size_t)n * 128 + f - 4];
                else              v = chars[(size_t)n * 256 + f - 132];
            }
            As[kk][m] = v;
        }
#pragma unroll
        for (int j = 0; j < 8; j++) {
            int e = tid + j * 256;
            int kk = e >> 7, n = e & 127;
            int f = fbase + kk;
            Bs[kk][n] = (f < NFEAT) ? Wf[(size_t)f * AS + n] : 0.f;
        }
        __syncthreads();
#pragma unroll
        for (int kk = 0; kk < 16; kk++) {
            float4 a4 = *(const float4*)&As[kk][ty * 4];
            float4 b4 = *(const float4*)&Bs[kk][tx * 4];
            float av[4] = { a4.x, a4.y, a4.z, a4.w };
            float bv[4] = { b4.x, b4.y, b4.z, b4.w };
#pragma unroll
            for (int i = 0; i < 4; i++)
#pragma unroll
                for (int j = 0; j < 4; j++) acc[i][j] += av[i] * bv[j];
        }
        __syncthreads();
    }
    float4 bfv = *(const float4*)&bf[tx * 4];
#pragma unroll
    for (int i = 0; i < 4; i++) {
        int n = m0 + ty * 4 + i;
        int t = g_tok[n];
        float4 qv;
        qv.x = acc[i][0] + bfv.x; qv.y = acc[i][1] + bfv.y;
        qv.z = acc[i][2] + bfv.z; qv.w = acc[i][3] + bfv.w;
        *(float4*)&out_q[(size_t)n * AS + tx * 4] = qv;
        float4 sv = *(const float4*)&g_s2c[(size_t)t * AS + tx * 4];
        float4 cv = { qv.x + sv.x, qv.y + sv.y, qv.z + sv.z, qv.w + sv.w };
        *(float4*)&out_c[(size_t)n * AS + tx * 4] = cv;
    }
}

// ---- kernel 4: cq = relu(c)@W_cq, ck = relu(c)@W_ck ----
__global__ void cqck_kernel(const float* __restrict__ c,
                            const float* __restrict__ Wcq, const float* __restrict__ Wck) {
    __shared__ float cs[32 * 128];
    __shared__ float ws[128 * 32];
    int tid = threadIdx.x, a0 = blockIdx.x * 32;
    for (int i = tid; i < 32 * 128; i += 128) cs[i] = fmaxf(c[(size_t)a0 * 128 + i], 0.f);
    for (int i = tid; i < 128 * 32; i += 128) {
        int f = i >> 5, j = i & 31;
        ws[i] = (j < 16) ? Wcq[f * 16 + j] : Wck[f * 16 + (j - 16)];
    }
    __syncthreads();
#pragma unroll
    for (int it = 0; it < 8; it++) {
        int idx = tid + it * 128;
        int a = idx >> 5, j = idx & 31;
        float s = 0.f;
        const float* cr = &cs[a * 128];
        for (int f = 0; f < 128; f++) s += cr[f] * ws[f * 32 + j];
        if (j < 16) g_cq[(a0 + a) * 16 + j] = s;
        else        g_ck[(a0 + a) * 16 + (j - 16)] = s;
    }
}

// ---- kernel 5: main p kernel, one CTA per block k ----
struct alignas(16) SmemP {
    float tile[1024 * 17];
    float ck[128 * 17];
    float cq[32 * 16];
    float wz2pT[16 * 128];
    float wposT[48];
    float wdist[16];
    float wmask[16];
    float wm1[256], wm2[256], wm3[256];
    float lnzg[128], lnzb[128];
    float posq[32 * 4];
    float posk[128 * 4];
    int   uidq[32], uidk[128];
    int   qt[32], kt[128];
    int   qi[32], ki[128];
    int   uqt[32], ukt[128];
    int   nq, nkc[4];
    unsigned char mq[32], mk[128];
};

__global__ void __launch_bounds__(512) p_kernel(
    const float* __restrict__ z, const float* __restrict__ pos,
    const int* __restrict__ maskw, const int* __restrict__ uid,
    const float* __restrict__ Wpos, const float* __restrict__ Wdist_,
    const float* __restrict__ Wmask_,
    const float* __restrict__ lnzg, const float* __restrict__ lnzb,
    const float* __restrict__ Wz2p,
    const float* __restrict__ Wm1, const float* __restrict__ Wm2,
    const float* __restrict__ Wm3,
    float* __restrict__ outp) {
    extern __shared__ char smraw[];
    SmemP& sm = *reinterpret_cast<SmemP*>(smraw);
    const int tid = threadIdx.x;
    const int k = blockIdx.x;

    if (tid < 128) {
        int l = tid, a = k * 32 + l - 48;
        bool valid = (a >= 0 && a < NA);
        sm.kt[l]   = valid ? g_tok[a] : -1;
        sm.uidk[l] = valid ? uid[a]   : -1;
        sm.mk[l]   = valid ? (maskw[a] != 0) : 0;   // 4-byte read: works for int32 or fp32 bool
        sm.posk[l * 4 + 0] = valid ? pos[a * 3 + 0] : 0.f;
        sm.posk[l * 4 + 1] = valid ? pos[a * 3 + 1] : 0.f;
        sm.posk[l * 4 + 2] = valid ? pos[a * 3 + 2] : 0.f;
    }
    if (tid < 32) {
        int a = k * 32 + tid;
        sm.qt[tid] = g_tok[a];
        sm.uidq[tid] = uid[a];
        sm.mq[tid] = (maskw[a] != 0);
        sm.posq[tid * 4 + 0] = pos[a * 3 + 0];
        sm.posq[tid * 4 + 1] = pos[a * 3 + 1];
        sm.posq[tid * 4 + 2] = pos[a * 3 + 2];
    }
    for (int i = tid; i < 128 * 16; i += 512) {
        int l = i >> 4, o = i & 15;
        int a = k * 32 + l - 48;
        sm.ck[l * 17 + o] = (a >= 0 && a < NA) ? g_ck[a * 16 + o] : 0.f;
    }
    for (int i = tid; i < 32 * 16; i += 512) sm.cq[i] = g_cq[(k * 32) * 16 + i];
    for (int i = tid; i < 16 * 128; i += 512) {
        int o = i >> 7, f = i & 127;
        sm.wz2pT[i] = Wz2p[f * 16 + o];
    }
    if (tid < 48) sm.wposT[tid] = Wpos[tid];
    if (tid >= 64 && tid < 80)  sm.wdist[tid - 64] = Wdist_[tid - 64];
    if (tid >= 96 && tid < 112) sm.wmask[tid - 96] = Wmask_[tid - 96];
    if (tid >= 128 && tid < 384) sm.wm1[tid - 128] = Wm1[tid - 128];
    for (int i = tid; i < 256; i += 512) { sm.wm2[i] = Wm2[i]; sm.wm3[i] = Wm3[i]; }
    for (int i = tid; i < 128; i += 512) { sm.lnzg[i] = lnzg[i]; sm.lnzb[i] = lnzb[i]; }
    __syncthreads();

    if (tid == 0) {
        int n = 0, last = -1;
        for (int w = 0; w < 32; w++) {
            int t = sm.qt[w];
            if (n == 0 || t != last) { sm.uqt[n++] = t; last = t; }
            sm.qi[w] = n - 1;
        }
        sm.nq = n;
        for (int c2 = 0; c2 < 4; c2++) {
            int nn = 0; last = -1;
            for (int j = 0; j < 32; j++) {
                int l = c2 * 32 + j, t = sm.kt[l];
                if (t < 0) { sm.ki[l] = -1; continue; }
                if (nn == 0 || t != last) { sm.ukt[c2 * 32 + nn] = t; last = t; nn++; }
                sm.ki[l] = nn - 1;
            }
            sm.nkc[c2] = nn;
        }
    }
    __syncthreads();

    const int wid = tid >> 5, lane = tid & 31;
    const int nq = sm.nq;

    for (int lc = 0; lc < 4; lc++) {
        if (lc) __syncthreads();
        const int nk = sm.nkc[lc];
        const int npairs = nq * nk;

        for (int p = wid; p < npairs; p += 16) {
            int ti = sm.uqt[p / nk];
            int tj = sm.ukt[lc * 32 + p % nk];
            const float4* zr = reinterpret_cast<const float4*>(z + ((size_t)ti * TT + tj) * 128);
            float4 v = zr[lane];
            float s = v.x + v.y + v.z + v.w;
            float q = v.x * v.x + v.y * v.y + v.z * v.z + v.w * v.w;
#pragma unroll
            for (int d = 16; d; d >>= 1) { s += __shfl_xor_sync(~0u, s, d); q += __shfl_xor_sync(~0u, q, d); }
            float mean = s * (1.f / 128.f);
            float rstd = rsqrtf(q * (1.f / 128.f) - mean * mean + 1e-5f);
            float4 g4 = reinterpret_cast<const float4*>(sm.lnzg)[lane];
            float4 b4 = reinterpret_cast<const float4*>(sm.lnzb)[lane];
            float n0 = (v.x - mean) * rstd * g4.x + b4.x;
            float n1 = (v.y - mean) * rstd * g4.y + b4.y;
            float n2 = (v.z - mean) * rstd * g4.z + b4.z;
            float n3 = (v.w - mean) * rstd * g4.w + b4.w;
            float pp[16];
#pragma unroll
            for (int o = 0; o < 16; o++) {
                float4 w = reinterpret_cast<const float4*>(sm.wz2pT + o * 128)[lane];
                pp[o] = n0 * w.x + n1 * w.y + n2 * w.z + n3 * w.w;
            }
#pragma unroll
            for (int d = 16; d; d >>= 1)
#pragma unroll
                for (int o = 0; o < 16; o++) pp[o] += __shfl_xor_sync(~0u, pp[o], d);
            if (lane < 16) sm.tile[p * 17 + lane] = pp[lane];
        }
        __syncthreads();

#pragma unroll 1
        for (int half = 0; half < 2; half++) {
            int idx = tid + half * 512;
            int w = idx >> 5, ll = idx & 31, l = lc * 32 + ll;
            float acc[16];
            const float* cqr = sm.cq + w * 16;
#pragma unroll
            for (int o = 0; o < 16; o++) acc[o] = cqr[o];
            int ktl = sm.kt[l];
            if (ktl >= 0) {
                const float* ckr = sm.ck + l * 17;
                const float* tr = sm.tile + (sm.qi[w] * nk + sm.ki[l]) * 17;
#pragma unroll
                for (int o = 0; o < 16; o++) acc[o] += ckr[o] + tr[o];
                if (sm.mk[l] && sm.mq[w] && sm.uidk[l] == sm.uidq[w]) {
                    float dx = sm.posk[l * 4 + 0] - sm.posq[w * 4 + 0];
                    float dy = sm.posk[l * 4 + 1] - sm.posq[w * 4 + 1];
                    float dz = sm.posk[l * 4 + 2] - sm.posq[w * 4 + 2];
                    float dn = 1.f / (1.f + dx * dx + dy * dy + dz * dz);
#pragma unroll
                    for (int o = 0; o < 16; o++)
                        acc[o] += dx * sm.wposT[o] + dy * sm.wposT[16 + o] +
                                  dz * sm.wposT[32 + o] + dn * sm.wdist[o] + sm.wmask[o];
                }
            }
            // 3-layer 16x16 MLP
            float t1[16], t2[16];
#pragma unroll
            for (int j = 0; j < 16; j++) t1[j] = 0.f;
#pragma unroll
            for (int o = 0; o < 16; o++) {
                float r = fmaxf(acc[o], 0.f);
#pragma unroll
                for (int j = 0; j < 16; j++) t1[j] += r * sm.wm1[o * 16 + j];
            }
#pragma unroll
            for (int j = 0; j < 16; j++) t2[j] = 0.f;
#pragma unroll
            for (int o = 0; o < 16; o++) {
                float r = fmaxf(t1[o], 0.f);
#pragma unroll
                for (int j = 0; j < 16; j++) t2[j] += r * sm.wm2[o * 16 + j];
            }
#pragma unroll
            for (int j = 0; j < 16; j++) {
                float r = fmaxf(t2[j], 0.f);
#pragma unroll
                for (int o = 0; o < 16; o++) acc[o] += r * sm.wm3[j * 16 + o];
            }
            float* po = outp + (((size_t)(k * 32 + w)) * 128 + l) * 16;
#pragma unroll
            for (int oq = 0; oq < 4; oq++) {
                float4 v4 = { acc[oq * 4], acc[oq * 4 + 1], acc[oq * 4 + 2], acc[oq * 4 + 3] };
                reinterpret_cast<float4*>(po)[oq] = v4;
            }
        }
    }
}

extern "C" void kernel_launch(void* const* d_in, const int* in_sizes, int n_in,
                              void* d_out, int out_size) {
    const float* ref_pos      = (const float*)d_in[0];
    const float* ref_charge   = (const float*)d_in[1];
    const float* ref_element  = (const float*)d_in[2];
    const float* ref_chars    = (const float*)d_in[3];
    const int*   mask         = (const int*)d_in[4];
    const int*   uid          = (const int*)d_in[5];
    const float* a2t          = (const float*)d_in[6];
    const float* s_trunk      = (const float*)d_in[7];
    const float* z            = (const float*)d_in[8];
    const float* W_feat       = (const float*)d_in[9];
    const float* b_feat       = (const float*)d_in[10];
    const float* W_pos        = (const float*)d_in[11];
    const float* W_dist       = (const float*)d_in[12];
    const float* W_mask       = (const float*)d_in[13];
    const float* ln_s_g       = (const float*)d_in[14];
    const float* ln_s_b       = (const float*)d_in[15];
    const float* W_s2c        = (const float*)d_in[16];
    const float* ln_z_g       = (const float*)d_in[17];
    const float* ln_z_b       = (const float*)d_in[18];
    const float* W_z2p        = (const float*)d_in[19];
    const float* W_cq         = (const float*)d_in[20];
    const float* W_ck         = (const float*)d_in[21];
    const float* W_m1         = (const float*)d_in[22];
    const float* W_m2         = (const float*)d_in[23];
    const float* W_m3         = (const float*)d_in[24];

    float* out_q = (float*)d_out;
    float* out_c = out_q + (size_t)NA * AS;
    float* out_p = out_q + (size_t)2 * NA * AS;

    cudaFuncSetAttribute(p_kernel, cudaFuncAttributeMaxDynamicSharedMemorySize,
                         (int)sizeof(SmemP));

    tok_kernel<<<512, 256>>>(a2t);
    s2c_kernel<<<128, 256>>>(s_trunk, ln_s_g, ln_s_b, W_s2c);
    c0_kernel<<<128, 256>>>(ref_pos, ref_charge, ref_element, ref_chars,
                            W_feat, b_feat, out_q, out_c);
    cqck_kernel<<<128, 128>>>(out_c, W_cq, W_ck);
    p_kernel<<<128, 512, sizeof(SmemP)>>>(z, ref_pos, mask, uid,
                                          W_pos, W_dist, W_mask,
                                          ln_z_g, ln_z_b, W_z2p,
                                          W_m1, W_m2, W_m3, out_p);
}

// round 6
// speedup vs baseline: 1.0328x; 1.0328x over previous
#include <cuda_runtime.h>
#include <cstdint>
#include <cstddef>

#define NA 4096
#define TT 512
#define TS 384
#define AS 128
#define AZ 16
#define NFEAT 388

typedef unsigned long long ull;

__device__ int   g_tok[NA];
__device__ float g_s2c[TT * AS];
__device__ float g_cq[NA * AZ];
__device__ float g_ck[NA * AZ];

// ---- packed f32x2 helpers ----
__device__ __forceinline__ ull pk2(float lo, float hi) {
    ull r; asm("mov.b64 %0,{%1,%2};" : "=l"(r) : "f"(lo), "f"(hi)); return r;
}
__device__ __forceinline__ void upk2(ull v, float& lo, float& hi) {
    asm("mov.b64 {%0,%1},%2;" : "=f"(lo), "=f"(hi) : "l"(v));
}
__device__ __forceinline__ ull fma2(ull a, ull b, ull c) {
    ull r; asm("fma.rn.f32x2 %0,%1,%2,%3;" : "=l"(r) : "l"(a), "l"(b), "l"(c)); return r;
}
__device__ __forceinline__ ull relu2(ull v) {
    float lo, hi; upk2(v, lo, hi);
    return pk2(fmaxf(lo, 0.f), fmaxf(hi, 0.f));
}

// ---- kernel 1: token id per atom (argmax of one-hot row) ----
__global__ void tok_kernel(const float* __restrict__ a2t) {
    int row = blockIdx.x * 8 + (threadIdx.x >> 5);
    int lane = threadIdx.x & 31;
    if (row >= NA) return;
    const float* r = a2t + (size_t)row * TT;
    int found = -1;
    for (int j = lane; j < TT; j += 32)
        if (r[j] > 0.5f) found = j;
#pragma unroll
    for (int d = 16; d; d >>= 1) found = max(found, __shfl_xor_sync(~0u, found, d));
    if (lane == 0) g_tok[row] = found;
}

// ---- kernel 2: s2c = LN(s_trunk) @ W_s2c ----
__global__ void s2c_kernel(const float* __restrict__ s_trunk,
                           const float* __restrict__ g, const float* __restrict__ b,
                           const float* __restrict__ W) {
    __shared__ float srow[4 * TS];
    __shared__ float mu[4], rsd[4];
    int r0 = blockIdx.x * 4, tid = threadIdx.x;
    for (int i = tid; i < 4 * TS; i += 256) srow[i] = s_trunk[(size_t)r0 * TS + i];
    __syncthreads();
    int wid = tid >> 5, lane = tid & 31;
    if (wid < 4) {
        float s = 0.f, q = 0.f;
        for (int f = lane; f < TS; f += 32) { float v = srow[wid * TS + f]; s += v; q += v * v; }
#pragma unroll
        for (int d = 16; d; d >>= 1) { s += __shfl_xor_sync(~0u, s, d); q += __shfl_xor_sync(~0u, q, d); }
        if (lane == 0) { float m = s / TS; mu[wid] = m; rsd[wid] = rsqrtf(q / TS - m * m + 1e-5f); }
    }
    __syncthreads();
    for (int i = tid; i < 4 * TS; i += 256) {
        int r = i / TS, f = i - r * TS;
        srow[i] = (srow[i] - mu[r]) * rsd[r] * g[f] + b[f];
    }
    __syncthreads();
    int o = tid & 127, hp = tid >> 7;
    const float* ra = &srow[(hp * 2) * TS];
    const float* rb = &srow[(hp * 2 + 1) * TS];
    float a0 = 0.f, a1 = 0.f;
    for (int f = 0; f < TS; f++) {
        float w = W[(size_t)f * AS + o];
        a0 += ra[f] * w; a1 += rb[f] * w;
    }
    g_s2c[(r0 + hp * 2) * AS + o] = a0;
    g_s2c[(r0 + hp * 2 + 1) * AS + o] = a1;
}

// ---- kernel 3: c0 = feats@W_feat+b ; q, c outputs ; fused cq/ck ----
// region1 (18944B): As[16][40] floats then Bsp[16*128] ull  — aliased later by ws[128*32] floats
#define C0_REGION1 18944
__global__ void __launch_bounds__(256) c0_kernel(
    const float* __restrict__ pos, const float* __restrict__ charge,
    const float* __restrict__ elem, const float* __restrict__ chars,
    const float* __restrict__ Wf, const float* __restrict__ bf,
    const float* __restrict__ Wcq, const float* __restrict__ Wck,
    float* __restrict__ out_q, float* __restrict__ out_c) {
    __shared__ __align__(16) char buf[C0_REGION1];
    __shared__ float cs[32][129];
    float (*As)[40] = (float(*)[40])buf;
    ull* Bsp = (ull*)(buf + 16 * 40 * 4);
    float* ws = (float*)buf;

    int tid = threadIdx.x, ty = tid >> 5, tx = tid & 31;
    int m0 = blockIdx.x * 32;
    ull acc2[2][4] = {};
    for (int kt = 0; kt < 25; kt++) {
        int fbase = kt * 16;
#pragma unroll
        for (int j = 0; j < 2; j++) {
            int e = tid + j * 256;
            int kk = e & 15, m = e >> 4;
            int f = fbase + kk, n = m0 + m;
            float v = 0.f;
            if (f < NFEAT) {
                if (f < 3)        v = pos[n * 3 + f];
                else if (f == 3)  v = charge[n];
                else if (f < 132) v = elem[(size_t)n * 128 + f - 4];
                else              v = chars[(size_t)n * 256 + f - 132];
            }
            As[kk][m] = v;
        }
#pragma unroll
        for (int j = 0; j < 8; j++) {
            int e = tid + j * 256;
            int kk = e >> 7, n = e & 127;
            int f = fbase + kk;
            float v = (f < NFEAT) ? Wf[(size_t)f * AS + n] : 0.f;
            Bsp[kk * 128 + n] = pk2(v, v);
        }
        __syncthreads();
#pragma unroll
        for (int kk = 0; kk < 16; kk++) {
            ull a01 = *(const ull*)&As[kk][ty * 4];
            ull a23 = *(const ull*)&As[kk][ty * 4 + 2];
            const ull* brow = Bsp + kk * 128 + tx * 4;
#pragma unroll
            for (int j = 0; j < 4; j++) {
                ull bb = brow[j];
                acc2[0][j] = fma2(a01, bb, acc2[0][j]);
                acc2[1][j] = fma2(a23, bb, acc2[1][j]);
            }
        }
        __syncthreads();
    }
    // ws (aliases As/Bsp) — safe: all GEMM smem reads complete before last sync
    for (int i = tid; i < 128 * 32; i += 256) {
        int f = i >> 5, j = i & 31;
        ws[i] = (j < 16) ? Wcq[f * 16 + j] : Wck[f * 16 + (j - 16)];
    }
    float accf[4][4];
#pragma unroll
    for (int j = 0; j < 4; j++) {
        upk2(acc2[0][j], accf[0][j], accf[1][j]);
        upk2(acc2[1][j], accf[2][j], accf[3][j]);
    }
    float4 bfv = *(const float4*)&bf[tx * 4];
#pragma unroll
    for (int i = 0; i < 4; i++) {
        int n = m0 + ty * 4 + i;
        int t = g_tok[n];
        float4 qv;
        qv.x = accf[i][0] + bfv.x; qv.y = accf[i][1] + bfv.y;
        qv.z = accf[i][2] + bfv.z; qv.w = accf[i][3] + bfv.w;
        *(float4*)&out_q[(size_t)n * AS + tx * 4] = qv;
        float4 sv = *(const float4*)&g_s2c[(size_t)t * AS + tx * 4];
        float4 cv = { qv.x + sv.x, qv.y + sv.y, qv.z + sv.z, qv.w + sv.w };
        *(float4*)&out_c[(size_t)n * AS + tx * 4] = cv;
        int a = ty * 4 + i;
        cs[a][tx * 4 + 0] = fmaxf(cv.x, 0.f);
        cs[a][tx * 4 + 1] = fmaxf(cv.y, 0.f);
        cs[a][tx * 4 + 2] = fmaxf(cv.z, 0.f);
        cs[a][tx * 4 + 3] = fmaxf(cv.w, 0.f);
    }
    __syncthreads();
    // fused cq/ck: thread = (atom a, j-group)
    {
        int a = tid >> 3, jg = tid & 7, j0 = jg * 4;
        float4 a4 = { 0.f, 0.f, 0.f, 0.f };
#pragma unroll 8
        for (int f = 0; f < 128; f++) {
            float r = cs[a][f];
            float4 w4 = *(const float4*)&ws[f * 32 + j0];
            a4.x += r * w4.x; a4.y += r * w4.y; a4.z += r * w4.z; a4.w += r * w4.w;
        }
        if (j0 < 16) *(float4*)&g_cq[(m0 + a) * 16 + j0] = a4;
        else         *(float4*)&g_ck[(m0 + a) * 16 + (j0 - 16)] = a4;
    }
}

// ---- kernel 4: main p kernel, one CTA per block k ----
struct alignas(16) SmemP {
    ull   wm1p[256], wm2p[256], wm3p[256];
    float tile[1024 * 17];
    float ck[128 * 17];
    float cq[32 * 16];
    float wz2pT[16 * 128];
    float wposT[48];
    float wdist[16];
    float wmask[16];
    float lnzg[128], lnzb[128];
    float posq[32 * 4];
    float posk[128 * 4];
    int   uidq[32], uidk[128];
    int   qt[32], kt[128];
    int   qi[32], ki[128];
    int   uqt[32], ukt[128];
    int   nq, nkc[4];
    unsigned char mq[32], mk[128];
};

__device__ __forceinline__ void preacc(const SmemP& sm, int w, int l, int nk,
                                       int ktl, float* acc) {
    const float* cqr = sm.cq + w * 16;
#pragma unroll
    for (int o = 0; o < 16; o++) acc[o] = cqr[o];
    if (ktl >= 0) {
        const float* ckr = sm.ck + l * 17;
        const float* tr = sm.tile + (sm.qi[w] * nk + sm.ki[l]) * 17;
#pragma unroll
        for (int o = 0; o < 16; o++) acc[o] += ckr[o] + tr[o];
        if (sm.mk[l] && sm.mq[w] && sm.uidk[l] == sm.uidq[w]) {
            float dx = sm.posk[l * 4 + 0] - sm.posq[w * 4 + 0];
            float dy = sm.posk[l * 4 + 1] - sm.posq[w * 4 + 1];
            float dz = sm.posk[l * 4 + 2] - sm.posq[w * 4 + 2];
            float dn = 1.f / (1.f + dx * dx + dy * dy + dz * dz);
#pragma unroll
            for (int o = 0; o < 16; o++)
                acc[o] += dx * sm.wposT[o] + dy * sm.wposT[16 + o] +
                          dz * sm.wposT[32 + o] + dn * sm.wdist[o] + sm.wmask[o];
        }
    }
}

__global__ void __launch_bounds__(512) p_kernel(
    const float* __restrict__ z, const float* __restrict__ pos,
    const int* __restrict__ maskw, const int* __restrict__ uid,
    const float* __restrict__ Wpos, const float* __restrict__ Wdist_,
    const float* __restrict__ Wmask_,
    const float* __restrict__ lnzg, const float* __restrict__ lnzb,
    const float* __restrict__ Wz2p,
    const float* __restrict__ Wm1, const float* __restrict__ Wm2,
    const float* __restrict__ Wm3,
    float* __restrict__ outp) {
    extern __shared__ char smraw[];
    SmemP& sm = *reinterpret_cast<SmemP*>(smraw);
    const int tid = threadIdx.x;
    const int k = blockIdx.x;

    if (tid < 128) {
        int l = tid, a = k * 32 + l - 48;
        bool valid = (a >= 0 && a < NA);
        sm.kt[l]   = valid ? g_tok[a] : -1;
        sm.uidk[l] = valid ? uid[a]   : -1;
        sm.mk[l]   = valid ? (maskw[a] != 0) : 0;
        sm.posk[l * 4 + 0] = valid ? pos[a * 3 + 0] : 0.f;
        sm.posk[l * 4 + 1] = valid ? pos[a * 3 + 1] : 0.f;
        sm.posk[l * 4 + 2] = valid ? pos[a * 3 + 2] : 0.f;
    }
    if (tid < 32) {
        int a = k * 32 + tid;
        sm.qt[tid] = g_tok[a];
        sm.uidq[tid] = uid[a];
        sm.mq[tid] = (maskw[a] != 0);
        sm.posq[tid * 4 + 0] = pos[a * 3 + 0];
        sm.posq[tid * 4 + 1] = pos[a * 3 + 1];
        sm.posq[tid * 4 + 2] = pos[a * 3 + 2];
    }
    for (int i = tid; i < 128 * 16; i += 512) {
        int l = i >> 4, o = i & 15;
        int a = k * 32 + l - 48;
        sm.ck[l * 17 + o] = (a >= 0 && a < NA) ? g_ck[a * 16 + o] : 0.f;
    }
    for (int i = tid; i < 32 * 16; i += 512) sm.cq[i] = g_cq[(k * 32) * 16 + i];
    for (int i = tid; i < 16 * 128; i += 512) {
        int o = i >> 7, f = i & 127;
        sm.wz2pT[i] = Wz2p[f * 16 + o];
    }
    if (tid < 48) sm.wposT[tid] = Wpos[tid];
    if (tid >= 64 && tid < 80)  sm.wdist[tid - 64] = Wdist_[tid - 64];
    if (tid >= 96 && tid < 112) sm.wmask[tid - 96] = Wmask_[tid - 96];
    for (int i = tid; i < 256; i += 512) {
        float w1 = Wm1[i], w2 = Wm2[i], w3 = Wm3[i];
        sm.wm1p[i] = pk2(w1, w1);
        sm.wm2p[i] = pk2(w2, w2);
        sm.wm3p[i] = pk2(w3, w3);
    }
    for (int i = tid; i < 128; i += 512) { sm.lnzg[i] = lnzg[i]; sm.lnzb[i] = lnzb[i]; }
    __syncthreads();

    if (tid == 0) {
        int n = 0, last = -1;
        for (int w = 0; w < 32; w++) {
            int t = sm.qt[w];
            if (n == 0 || t != last) { sm.uqt[n++] = t; last = t; }
            sm.qi[w] = n - 1;
        }
        sm.nq = n;
        for (int c2 = 0; c2 < 4; c2++) {
            int nn = 0; last = -1;
            for (int j = 0; j < 32; j++) {
                int l = c2 * 32 + j, t = sm.kt[l];
                if (t < 0) { sm.ki[l] = -1; continue; }
                if (nn == 0 || t != last) { sm.ukt[c2 * 32 + nn] = t; last = t; nn++; }
                sm.ki[l] = nn - 1;
            }
            sm.nkc[c2] = nn;
        }
    }
    __syncthreads();

    const int wid = tid >> 5, lane = tid & 31;
    const int nq = sm.nq;

    for (int lc = 0; lc < 4; lc++) {
        if (lc) __syncthreads();
        const int nk = sm.nkc[lc];
        const int npairs = nq * nk;

        for (int p = wid; p < npairs; p += 16) {
            int ti = sm.uqt[p / nk];
            int tj = sm.ukt[lc * 32 + p % nk];
            const float4* zr = reinterpret_cast<const float4*>(z + ((size_t)ti * TT + tj) * 128);
            float4 v = zr[lane];
            float s = v.x + v.y + v.z + v.w;
            float q = v.x * v.x + v.y * v.y + v.z * v.z + v.w * v.w;
#pragma unroll
            for (int d = 16; d; d >>= 1) { s += __shfl_xor_sync(~0u, s, d); q += __shfl_xor_sync(~0u, q, d); }
            float mean = s * (1.f / 128.f);
            float rstd = rsqrtf(q * (1.f / 128.f) - mean * mean + 1e-5f);
            float4 g4 = reinterpret_cast<const float4*>(sm.lnzg)[lane];
            float4 b4 = reinterpret_cast<const float4*>(sm.lnzb)[lane];
            float n0 = (v.x - mean) * rstd * g4.x + b4.x;
            float n1 = (v.y - mean) * rstd * g4.y + b4.y;
            float n2 = (v.z - mean) * rstd * g4.z + b4.z;
            float n3 = (v.w - mean) * rstd * g4.w + b4.w;
            float pp[16];
#pragma unroll
            for (int o = 0; o < 16; o++) {
                float4 w = reinterpret_cast<const float4*>(sm.wz2pT + o * 128)[lane];
                pp[o] = n0 * w.x + n1 * w.y + n2 * w.z + n3 * w.w;
            }
#pragma unroll
            for (int d = 16; d; d >>= 1)
#pragma unroll
                for (int o = 0; o < 16; o++) pp[o] += __shfl_xor_sync(~0u, pp[o], d);
            if (lane < 16) sm.tile[p * 17 + lane] = pp[lane];
        }
        __syncthreads();

        // 1024 (w,l) pairs: thread handles (wid, l) and (wid+16, l) packed f32x2
        {
            const int l = lc * 32 + lane;
            const int ktl = sm.kt[l];
            float accA[16], accB[16];
            preacc(sm, wid, l, nk, ktl, accA);
            preacc(sm, wid + 16, l, nk, ktl, accB);
            ull acc2[16];
#pragma unroll
            for (int o = 0; o < 16; o++) acc2[o] = pk2(accA[o], accB[o]);

            ull t1[16];
#pragma unroll
            for (int j = 0; j < 16; j++) t1[j] = 0ull;
#pragma unroll
            for (int o = 0; o < 16; o++) {
                ull r2 = relu2(acc2[o]);
#pragma unroll
                for (int j = 0; j < 16; j++) t1[j] = fma2(r2, sm.wm1p[o * 16 + j], t1[j]);
            }
            ull t2[16];
#pragma unroll
            for (int j = 0; j < 16; j++) t2[j] = 0ull;
#pragma unroll
            for (int o = 0; o < 16; o++) {
                ull r2 = relu2(t1[o]);
#pragma unroll
                for (int j = 0; j < 16; j++) t2[j] = fma2(r2, sm.wm2p[o * 16 + j], t2[j]);
            }
#pragma unroll
            for (int j = 0; j < 16; j++) {
                ull r2 = relu2(t2[j]);
#pragma unroll
                for (int o = 0; o < 16; o++) acc2[o] = fma2(r2, sm.wm3p[j * 16 + o], acc2[o]);
            }
#pragma unroll
            for (int o = 0; o < 16; o++) upk2(acc2[o], accA[o], accB[o]);
            float* poA = outp + (((size_t)(k * 32 + wid)) * 128 + l) * 16;
            float* poB = outp + (((size_t)(k * 32 + wid + 16)) * 128 + l) * 16;
#pragma unroll
            for (int oq = 0; oq < 4; oq++) {
                float4 vA = { accA[oq * 4], accA[oq * 4 + 1], accA[oq * 4 + 2], accA[oq * 4 + 3] };
                float4 vB = { accB[oq * 4], accB[oq * 4 + 1], accB[oq * 4 + 2], accB[oq * 4 + 3] };
                reinterpret_cast<float4*>(poA)[oq] = vA;
                reinterpret_cast<float4*>(poB)[oq] = vB;
            }
        }
    }
}

extern "C" void kernel_launch(void* const* d_in, const int* in_sizes, int n_in,
                              void* d_out, int out_size) {
    const float* ref_pos      = (const float*)d_in[0];
    const float* ref_charge   = (const float*)d_in[1];
    const float* ref_element  = (const float*)d_in[2];
    const float* ref_chars    = (const float*)d_in[3];
    const int*   mask         = (const int*)d_in[4];
    const int*   uid          = (const int*)d_in[5];
    const float* a2t          = (const float*)d_in[6];
    const float* s_trunk      = (const float*)d_in[7];
    const float* z            = (const float*)d_in[8];
    const float* W_feat       = (const float*)d_in[9];
    const float* b_feat       = (const float*)d_in[10];
    const float* W_pos        = (const float*)d_in[11];
    const float* W_dist       = (const float*)d_in[12];
    const float* W_mask       = (const float*)d_in[13];
    const float* ln_s_g       = (const float*)d_in[14];
    const float* ln_s_b       = (const float*)d_in[15];
    const float* W_s2c        = (const float*)d_in[16];
    const float* ln_z_g       = (const float*)d_in[17];
    const float* ln_z_b       = (const float*)d_in[18];
    const float* W_z2p        = (const float*)d_in[19];
    const float* W_cq         = (const float*)d_in[20];
    const float* W_ck         = (const float*)d_in[21];
    const float* W_m1         = (const float*)d_in[22];
    const float* W_m2         = (const float*)d_in[23];
    const float* W_m3         = (const float*)d_in[24];

    float* out_q = (float*)d_out;
    float* out_c = out_q + (size_t)NA * AS;
    float* out_p = out_q + (size_t)2 * NA * AS;

    cudaFuncSetAttribute(p_kernel, cudaFuncAttributeMaxDynamicSharedMemorySize,
                         (int)sizeof(SmemP));

    tok_kernel<<<512, 256>>>(a2t);
    s2c_kernel<<<128, 256>>>(s_trunk, ln_s_g, ln_s_b, W_s2c);
    c0_kernel<<<128, 256>>>(ref_pos, ref_charge, ref_element, ref_chars,
                            W_feat, b_feat, W_cq, W_ck, out_q, out_c);
    p_kernel<<<128, 512, sizeof(SmemP)>>>(z, ref_pos, mask, uid,
                                          W_pos, W_dist, W_mask,
                                          ln_z_g, ln_z_b, W_z2p,
                                          W_m1, W_m2, W_m3, out_p);
}